// round 12
// baseline (speedup 1.0000x reference)
#include <cuda_runtime.h>
#include <cuda_fp16.h>
#include <math.h>

#define NA 128
#define NB 2
#define EE 512
#define HH 1024
#define GG 50
#define MROWS (NA*NA*NB)          // 32768
#define AW ((size_t)MROWS*HH/2)   // u32 words per fp16 activation array
#define WW ((size_t)HH*HH/2)      // u32 words per fp16 weight matrix

// -------- device scratch (no allocations allowed) --------
__device__ float d_g[(size_t)MROWS*GG];
__device__ float d_PQ[2*NA*NB*HH];
__device__ float d_Wg[GG*HH];
__device__ float d_b0[HH];
__device__ float d_eP[NA*NB];
__device__ float d_part[(size_t)MROWS*16];     // per-(row, n-tile, col-half) partial dots
__device__ unsigned d_fHiA[AW];
__device__ unsigned d_fLoA[AW];
__device__ unsigned d_fHiB[AW];
__device__ unsigned d_fLoB[AW];
__device__ unsigned d_Wt[6*WW];

__device__ __forceinline__ float gelu_exact(float x) { return x * normcdff(x); }

__device__ __forceinline__ unsigned smem_u32(const void* p) {
    unsigned a;
    asm("{ .reg .u64 t; cvta.to.shared.u64 t, %1; cvt.u32.u64 %0, t; }" : "=r"(a) : "l"(p));
    return a;
}
__device__ __forceinline__ void cp16(unsigned saddr, const void* g) {
    asm volatile("cp.async.cg.shared.global [%0], [%1], 16;" :: "r"(saddr), "l"(g));
}
__device__ __forceinline__ void ldsm4(unsigned addr, unsigned* r) {
    asm volatile("ldmatrix.sync.aligned.m8n8.x4.shared.b16 {%0,%1,%2,%3}, [%4];"
                 : "=r"(r[0]), "=r"(r[1]), "=r"(r[2]), "=r"(r[3]) : "r"(addr));
}
__device__ __forceinline__ void mma16816(float* c, const unsigned* a, unsigned b0, unsigned b1) {
    asm volatile("mma.sync.aligned.m16n8k16.row.col.f32.f16.f16.f32 "
                 "{%0,%1,%2,%3}, {%4,%5,%6,%7}, {%8,%9}, {%0,%1,%2,%3};"
                 : "+f"(c[0]), "+f"(c[1]), "+f"(c[2]), "+f"(c[3])
                 : "r"(a[0]), "r"(a[1]), "r"(a[2]), "r"(a[3]), "r"(b0), "r"(b1));
}
__device__ __forceinline__ unsigned pack_hi(float v0, float v1, float& l0, float& l1) {
    __half a = __float2half_rn(v0), b = __float2half_rn(v1);
    l0 = v0 - __half2float(a);
    l1 = v1 - __half2float(b);
    return ((unsigned)__half_as_ushort(b) << 16) | __half_as_ushort(a);
}
__device__ __forceinline__ unsigned pack_lo(float l0, float l1) {
    return ((unsigned)__half_as_ushort(__float2half_rn(l1)) << 16)
         | __half_as_ushort(__float2half_rn(l0));
}
__device__ __forceinline__ unsigned pack_h(float v0, float v1) {
    return ((unsigned)__half_as_ushort(__float2half_rn(v1)) << 16)
         | __half_as_ushort(__float2half_rn(v0));
}
__device__ __forceinline__ float hf_lo(unsigned w) {
    return __half2float(__ushort_as_half((unsigned short)(w & 0xffffu)));
}
__device__ __forceinline__ float hf_hi(unsigned w) {
    return __half2float(__ushort_as_half((unsigned short)(w >> 16)));
}

// ================= prologue kernels =================
__global__ void rbf_kernel(const float* __restrict__ dist) {
    int idx = blockIdx.x * blockDim.x + threadIdx.x;
    if (idx >= MROWS * GG) return;
    int m = idx / GG, k = idx - m * GG;
    const float delta = 12.0f / 49.0f;
    const float coeff = -0.5f / (delta * delta);
    float t = dist[m] - delta * (float)k;
    d_g[idx] = expf(coeff * t * t);
}

__global__ void bias0_kernel(const float* __restrict__ Win3,
                             const float* __restrict__ bin,
                             const float* __restrict__ rbf_b) {
    int h = blockIdx.x * blockDim.x + threadIdx.x;
    if (h >= HH) return;
    float s = bin[h];
    for (int e = 0; e < EE; e++) s += rbf_b[e] * Win3[(size_t)e * HH + h];
    d_b0[h] = s;
}

#define SBM 64
#define SBN 64
#define SBK 16
__global__ __launch_bounds__(256)
void sgemm64(const float* __restrict__ A, const float* __restrict__ W,
             float* __restrict__ out, int M, int N, int K,
             size_t wstride, size_t ostride)
{
    W += blockIdx.z * wstride;
    out += blockIdx.z * ostride;
    __shared__ float As[SBK][SBM];
    __shared__ float Bs[SBK][SBN];
    int tid = threadIdx.x;
    int tx = tid & 15, ty = tid >> 4;
    int bm = blockIdx.x * SBM, bn = blockIdx.y * SBN;
    float acc[4][4] = {};
    int arow = tid >> 2, acol = (tid & 3) * 4;
    int brow = tid >> 4, bcol = (tid & 15) * 4;
    for (int k0 = 0; k0 < K; k0 += SBK) {
        float4 va = make_float4(0.f, 0.f, 0.f, 0.f);
        if (bm + arow < M) va = *(const float4*)(A + (size_t)(bm + arow) * K + k0 + acol);
        As[acol + 0][arow] = va.x; As[acol + 1][arow] = va.y;
        As[acol + 2][arow] = va.z; As[acol + 3][arow] = va.w;
        *(float4*)&Bs[brow][bcol] = *(const float4*)(W + (size_t)(k0 + brow) * N + bn + bcol);
        __syncthreads();
        #pragma unroll
        for (int kk = 0; kk < SBK; kk++) {
            float a[4], b[4];
            #pragma unroll
            for (int i = 0; i < 4; i++) a[i] = As[kk][ty * 4 + i];
            #pragma unroll
            for (int j = 0; j < 4; j++) b[j] = Bs[kk][tx * 4 + j];
            #pragma unroll
            for (int i = 0; i < 4; i++)
                #pragma unroll
                for (int j = 0; j < 4; j++)
                    acc[i][j] = fmaf(a[i], b[j], acc[i][j]);
        }
        __syncthreads();
    }
    #pragma unroll
    for (int i = 0; i < 4; i++) {
        int row = bm + ty * 4 + i;
        if (row < M)
            #pragma unroll
            for (int j = 0; j < 4; j++)
                out[(size_t)row * N + bn + tx * 4 + j] = acc[i][j];
    }
}

// h0: write gelu(g@Wg + P + Q + b0) directly as fp16 hi/lo split
__global__ __launch_bounds__(256)
void h0_kernel(unsigned* __restrict__ oHi, unsigned* __restrict__ oLo)
{
    __shared__ float Gs[64][52];
    __shared__ float Ws[52][64];
    int tid = threadIdx.x;
    int bm = blockIdx.x * 64, bn = blockIdx.y * 64;
    for (int idx = tid; idx < 64 * GG; idx += 256) {
        int r = idx / GG, k = idx - r * GG;
        Gs[r][k] = d_g[(size_t)(bm + r) * GG + k];
    }
    for (int idx = tid; idx < GG * 64; idx += 256) {
        int k = idx >> 6, n = idx & 63;
        Ws[k][n] = d_Wg[k * HH + bn + n];
    }
    __syncthreads();
    int tx = tid & 15, ty = tid >> 4;
    float acc[4][4] = {};
    #pragma unroll 10
    for (int k = 0; k < GG; k++) {
        float a[4], b[4];
        #pragma unroll
        for (int i = 0; i < 4; i++) a[i] = Gs[ty * 4 + i][k];
        #pragma unroll
        for (int j = 0; j < 4; j++) b[j] = Ws[k][tx * 4 + j];
        #pragma unroll
        for (int i = 0; i < 4; i++)
            #pragma unroll
            for (int j = 0; j < 4; j++)
                acc[i][j] = fmaf(a[i], b[j], acc[i][j]);
    }
    const float* P = d_PQ;
    const float* Q = d_PQ + NA * NB * HH;
    #pragma unroll
    for (int i = 0; i < 4; i++) {
        int m = bm + ty * 4 + i;
        int bb = m & (NB - 1);
        int jat = (m / NB) & (NA - 1);
        int iat = m / (NB * NA);
        int col0 = bn + tx * 4;
        float v[4];
        #pragma unroll
        for (int j = 0; j < 4; j++) {
            int col = col0 + j;
            float t = acc[i][j] + P[(iat * NB + bb) * HH + col]
                    + Q[(jat * NB + bb) * HH + col] + d_b0[col];
            v[j] = gelu_exact(t);
        }
        size_t wi = ((size_t)m * HH + col0) >> 1;
        float l0, l1, l2, l3;
        unsigned h0w = pack_hi(v[0], v[1], l0, l1);
        unsigned h1w = pack_hi(v[2], v[3], l2, l3);
        oHi[wi] = h0w; oHi[wi + 1] = h1w;
        oLo[wi] = pack_lo(l0, l1); oLo[wi + 1] = pack_lo(l2, l3);
    }
}

// weight prep: W[K][N] fp32 -> Wt[N][K] single fp16 (u32 k-pairs)
__global__ __launch_bounds__(256)
void prep_w(const float* __restrict__ We, const float* __restrict__ Wf,
            unsigned* __restrict__ wt)
{
    __shared__ float ts[64][33];
    int z = blockIdx.z;
    const float* W = (z < 3) ? We + (size_t)z * HH * HH : Wf + (size_t)(z - 3) * HH * HH;
    int k0 = blockIdx.x * 64, n0 = blockIdx.y * 32;
    int tid = threadIdx.x;
    #pragma unroll
    for (int i = 0; i < 8; i++) {
        int r = (tid >> 5) + i * 8, c = tid & 31;
        ts[r][c] = W[(size_t)(k0 + r) * HH + n0 + c];
    }
    __syncthreads();
    size_t zo = (size_t)z * WW;
    #pragma unroll
    for (int i = 0; i < 4; i++) {
        int on = (tid >> 5) + i * 8;
        int ok = tid & 31;
        float v0 = ts[ok * 2][on], v1 = ts[ok * 2 + 1][on];
        size_t oidx = zo + (size_t)(n0 + on) * (HH / 2) + (k0 >> 1) + ok;
        wt[oidx] = pack_h(v0, v1);
    }
}

// ========= fp16 2-pass mma GEMM layer, 64x64 warp tiles, 3-stage cp.async =========
// next = res + gelu((Ah+Al)@W^T + bias); res reconstructed from Ah/Al.
// CTA tile 128x128, 128 threads = 4 warps (2m x 2n), warp tile 64x64.
// Last layer: fused partial dot with Wout -> d_part[row*16 + nt_blk*2 + wn].
#define SMSTR 80                   // 64B data + 16B pad (conflict-free ldmatrix)
#define TILEB (128*SMSTR)          // 10240 B
#define NCHUNK 32
#define NSTAGE 3
#define STAGEB (3*TILEB)           // Ah, Al, B per stage
#define DSMEM_BYTES (NSTAGE*STAGEB)  // 92160

__global__ __launch_bounds__(128, 2)
void mma_layer(const uint4* __restrict__ Ah, const uint4* __restrict__ Al,
               const uint4* __restrict__ Bw,
               const float* __restrict__ bias,
               unsigned* __restrict__ oHi, unsigned* __restrict__ oLo,
               const float* __restrict__ wout, float* __restrict__ part,
               int lastLayer)
{
    extern __shared__ char dsm[];
    __shared__ float s_bias[128];
    __shared__ float s_wout[128];
    unsigned base = smem_u32(dsm);

    int tid = threadIdx.x;
    int nt_blk = blockIdx.x, mt_blk = blockIdx.y;
    s_bias[tid] = bias[nt_blk * 128 + tid];
    if (lastLayer) s_wout[tid] = wout[nt_blk * 128 + tid];

    int wid = tid >> 5, lane = tid & 31;
    int wm = wid & 1, wn = wid >> 1;

    float acc[4][8][4];
    #pragma unroll
    for (int i = 0; i < 4; i++)
        #pragma unroll
        for (int j = 0; j < 8; j++)
            #pragma unroll
            for (int k = 0; k < 4; k++) acc[i][j][k] = 0.f;

    const uint4* gAh = Ah + (size_t)(mt_blk * 128) * 128;   // 128 uint4 per row
    const uint4* gAl = Al + (size_t)(mt_blk * 128) * 128;
    const uint4* gB  = Bw + (size_t)(nt_blk * 128) * 128;

    // ldmatrix lane addressing
    int g = lane >> 3, lr = lane & 7;
    unsigned aoff0 = (unsigned)((wm * 64 + (g & 1) * 8 + lr) * SMSTR + (g >> 1) * 16);
    unsigned boff0 = (unsigned)((wn * 64 + (g >> 1) * 8 + lr) * SMSTR + (g & 1) * 16);

    // issue chunks 0 and 1
    #pragma unroll
    for (int pc = 0; pc < 2; pc++) {
        unsigned sb = base + pc * STAGEB;
        #pragma unroll
        for (int p = 0; p < 4; p++) {
            int idx = tid + p * 128;
            int row = idx >> 2, seg = idx & 3;
            unsigned off = (unsigned)(row * SMSTR + seg * 16);
            size_t src = (size_t)row * 128 + pc * 4 + seg;
            cp16(sb + off, gAh + src);
            cp16(sb + TILEB + off, gAl + src);
            cp16(sb + 2 * TILEB + off, gB + src);
        }
        asm volatile("cp.async.commit_group;");
    }

    int stage = 0;
    for (int kc = 0; kc < NCHUNK; kc++) {
        if (kc + 2 < NCHUNK) {
            int ps = (stage + 2) % NSTAGE;
            unsigned sb = base + ps * STAGEB;
            #pragma unroll
            for (int p = 0; p < 4; p++) {
                int idx = tid + p * 128;
                int row = idx >> 2, seg = idx & 3;
                unsigned off = (unsigned)(row * SMSTR + seg * 16);
                size_t src = (size_t)row * 128 + (kc + 2) * 4 + seg;
                cp16(sb + off, gAh + src);
                cp16(sb + TILEB + off, gAl + src);
                cp16(sb + 2 * TILEB + off, gB + src);
            }
            asm volatile("cp.async.commit_group;");
            asm volatile("cp.async.wait_group 2;");
        } else if (kc + 1 < NCHUNK) {
            asm volatile("cp.async.wait_group 1;");
        } else {
            asm volatile("cp.async.wait_group 0;");
        }
        __syncthreads();

        unsigned bb = base + stage * STAGEB;
        #pragma unroll
        for (int ks = 0; ks < 2; ks++) {
            unsigned kkb = ks * 32;   // 16 fp16 = 32 bytes
            unsigned ah[4][4], al[4][4], b[4][4];
            #pragma unroll
            for (int mt = 0; mt < 4; mt++) {
                unsigned ao = aoff0 + kkb + mt * (16 * SMSTR);
                ldsm4(bb + ao, ah[mt]);
                ldsm4(bb + TILEB + ao, al[mt]);
            }
            #pragma unroll
            for (int p = 0; p < 4; p++)
                ldsm4(bb + 2 * TILEB + boff0 + kkb + p * (16 * SMSTR), b[p]);
            #pragma unroll
            for (int mt = 0; mt < 4; mt++)
                #pragma unroll
                for (int nt = 0; nt < 8; nt++)
                    mma16816(acc[mt][nt], ah[mt], b[nt >> 1][(nt & 1) * 2], b[nt >> 1][(nt & 1) * 2 + 1]);
            #pragma unroll
            for (int mt = 0; mt < 4; mt++)
                #pragma unroll
                for (int nt = 0; nt < 8; nt++)
                    mma16816(acc[mt][nt], al[mt], b[nt >> 1][(nt & 1) * 2], b[nt >> 1][(nt & 1) * 2 + 1]);
        }
        __syncthreads();
        stage = (stage + 1) % NSTAGE;
    }

    // epilogue: residual reconstructed from A hi/lo at the output columns
    const unsigned* rAh = (const unsigned*)Ah;
    const unsigned* rAl = (const unsigned*)Al;
    #pragma unroll
    for (int mt = 0; mt < 4; mt++) {
        #pragma unroll
        for (int half = 0; half < 2; half++) {
            int row = mt_blk * 128 + wm * 64 + mt * 16 + half * 8 + (lane >> 2);
            float pdot = 0.f;
            #pragma unroll
            for (int nt = 0; nt < 8; nt++) {
                int cl = wn * 64 + nt * 8 + (lane & 3) * 2;
                size_t gi = (size_t)row * HH + nt_blk * 128 + cl;
                size_t wi = gi >> 1;
                unsigned hw = rAh[wi], lw = rAl[wi];
                float r0 = hf_lo(hw) + hf_lo(lw);
                float r1 = hf_hi(hw) + hf_hi(lw);
                float v0 = r0 + gelu_exact(acc[mt][nt][half * 2 + 0] + s_bias[cl]);
                float v1 = r1 + gelu_exact(acc[mt][nt][half * 2 + 1] + s_bias[cl + 1]);
                if (lastLayer) {
                    pdot += v0 * s_wout[cl] + v1 * s_wout[cl + 1];
                } else {
                    float l0, l1;
                    unsigned ohw = pack_hi(v0, v1, l0, l1);
                    oHi[wi] = ohw;
                    oLo[wi] = pack_lo(l0, l1);
                }
            }
            if (lastLayer) {
                pdot += __shfl_xor_sync(0xffffffffu, pdot, 1);
                pdot += __shfl_xor_sync(0xffffffffu, pdot, 2);
                if ((lane & 3) == 0)
                    part[(size_t)row * 16 + nt_blk * 2 + wn] = pdot;
            }
        }
    }
}

// ========= final reduction over partial dots (2MB input, deterministic) =========
__global__ __launch_bounds__(128)
void reduce2(const float* __restrict__ part, const float* __restrict__ bout,
             const int* __restrict__ mask, const float* __restrict__ vec_hat,
             float* __restrict__ out, int mode)
{
    __shared__ float sred[4][4];
    int tid = threadIdx.x;
    int jb = blockIdx.x;
    int j = jb / NB, b = jb % NB;
    int warp = tid >> 5, lane = tid & 31;
    float bo = bout[0];
    bool mj = mask[b * NA + j] != 0;

    int i = tid;   // 0..127 = one atom index each
    size_t m = ((size_t)(i * NA + j)) * NB + b;
    float dot = 0.f;
    #pragma unroll
    for (int t = 0; t < 16; t++) dot += part[m * 16 + t];
    float entry = (mj && mask[b * NA + i] != 0) ? 1.0f : 0.0f;
    float val = (dot + bo) * entry;

    float e = val, fx = 0.f, fy = 0.f, fz = 0.f;
    if (mode == 1) {
        const float* v = vec_hat + m * 3;
        fx = val * v[0]; fy = val * v[1]; fz = val * v[2];
    }
    #pragma unroll
    for (int o = 16; o > 0; o >>= 1) {
        e  += __shfl_xor_sync(0xffffffffu, e,  o);
        fx += __shfl_xor_sync(0xffffffffu, fx, o);
        fy += __shfl_xor_sync(0xffffffffu, fy, o);
        fz += __shfl_xor_sync(0xffffffffu, fz, o);
    }
    if (lane == 0) { sred[warp][0] = e; sred[warp][1] = fx; sred[warp][2] = fy; sred[warp][3] = fz; }
    __syncthreads();
    if (tid == 0) {
        float a0 = 0, a1 = 0, a2 = 0, a3 = 0;
        for (int w = 0; w < 4; w++) { a0 += sred[w][0]; a1 += sred[w][1]; a2 += sred[w][2]; a3 += sred[w][3]; }
        if (mode == 0) d_eP[jb] = a0;
        else {
            int o = 2 + (b * NA + j) * 3;
            out[o + 0] = a1 / 60.0f; out[o + 1] = a2 / 60.0f; out[o + 2] = a3 / 60.0f;
        }
    }
}

__global__ void energy_kernel(float* __restrict__ out) {
    int tid = threadIdx.x;
    int b = tid >> 5, lane = tid & 31;
    if (b >= NB) return;
    float s = 0.f;
    for (int j = lane; j < NA; j += 32) s += d_eP[j * NB + b];
    #pragma unroll
    for (int o = 16; o > 0; o >>= 1) s += __shfl_xor_sync(0xffffffffu, s, o);
    if (lane == 0) out[b] = s / 3600.0f;
}

// ========= launch =========
extern "C" void kernel_launch(void* const* d_in, const int* in_sizes, int n_in,
                              void* d_out, int out_size)
{
    const float* x       = (const float*)d_in[0];
    const float* dist    = (const float*)d_in[1];
    const float* vec_hat = (const float*)d_in[2];
    const int*   mask    = (const int*)d_in[3];   // bool promoted to int32
    const float* rbf_W   = (const float*)d_in[4];
    const float* rbf_b   = (const float*)d_in[5];
    const float* Win[2]  = {(const float*)d_in[6],  (const float*)d_in[12]};
    const float* bin[2]  = {(const float*)d_in[7],  (const float*)d_in[13]};
    const float* Wh[2]   = {(const float*)d_in[8],  (const float*)d_in[14]};
    const float* bh[2]   = {(const float*)d_in[9],  (const float*)d_in[15]};
    const float* Wout[2] = {(const float*)d_in[10], (const float*)d_in[16]};
    const float* bout[2] = {(const float*)d_in[11], (const float*)d_in[17]};
    int L = in_sizes[8] / (HH * HH);
    float* out = (float*)d_out;

    static int attr_set = 0;
    if (!attr_set) {
        cudaFuncSetAttribute(mma_layer, cudaFuncAttributeMaxDynamicSharedMemorySize, DSMEM_BYTES);
        attr_set = 1;
    }

    float *PQ, *Wg, *partp;
    unsigned *fHiA, *fLoA, *fHiB, *fLoB, *Wt;
    cudaGetSymbolAddress((void**)&PQ, d_PQ);
    cudaGetSymbolAddress((void**)&Wg, d_Wg);
    cudaGetSymbolAddress((void**)&partp, d_part);
    cudaGetSymbolAddress((void**)&fHiA, d_fHiA);
    cudaGetSymbolAddress((void**)&fLoA, d_fLoA);
    cudaGetSymbolAddress((void**)&fHiB, d_fHiB);
    cudaGetSymbolAddress((void**)&fLoB, d_fLoB);
    cudaGetSymbolAddress((void**)&Wt, d_Wt);

    rbf_kernel<<<(MROWS * GG + 255) / 256, 256>>>(dist);
    prep_w<<<dim3(16, 32, 6), 256>>>(Wh[0], Wh[1], Wt);

    for (int mlp = 0; mlp < 2; mlp++) {
        const float* W1 = Win[mlp];
        const float* W3 = Win[mlp] + (size_t)2 * EE * HH;

        // P and Q in one launch (z selects Win row-slice + output half)
        sgemm64<<<dim3(4, 16, 2), 256>>>(x, W1, PQ, NA * NB, HH, EE,
                                         (size_t)EE * HH, (size_t)NA * NB * HH);
        sgemm64<<<dim3(1, 16, 1), 256>>>(rbf_W, W3, Wg, GG, HH, EE, 0, 0);
        bias0_kernel<<<4, 256>>>(W3, bin[mlp], rbf_b);

        h0_kernel<<<dim3(MROWS / 64, HH / 64), 256>>>(fHiA, fLoA);

        unsigned* curHi = fHiA; unsigned* curLo = fLoA;
        unsigned* nxtHi = fHiB; unsigned* nxtLo = fLoB;
        for (int l = 0; l < L; l++) {
            size_t zo = (size_t)(mlp * 3 + l) * WW;
            int last = (l == L - 1) ? 1 : 0;
            mma_layer<<<dim3(HH / 128, MROWS / 128), 128, DSMEM_BYTES>>>(
                (const uint4*)curHi, (const uint4*)curLo,
                (const uint4*)(Wt + zo),
                bh[mlp] + (size_t)l * HH, nxtHi, nxtLo,
                Wout[mlp], partp, last);
            unsigned* t1 = curHi; curHi = nxtHi; nxtHi = t1;
            unsigned* t2 = curLo; curLo = nxtLo; nxtLo = t2;
        }

        reduce2<<<NA * NB, 128>>>(partp, bout[mlp], mask, vec_hat, out, mlp);
    }

    energy_kernel<<<1, 64>>>(out);
}

// round 13
// speedup vs baseline: 1.2429x; 1.2429x over previous
#include <cuda_runtime.h>
#include <cuda_fp16.h>
#include <math.h>

#define NA 128
#define NB 2
#define EE 512
#define HH 1024
#define GG 50
#define MROWS (NA*NA*NB)          // 32768
#define AW ((size_t)MROWS*HH/2)   // u32 words per fp16 activation array
#define WW ((size_t)HH*HH/2)      // u32 words per fp16 weight matrix

// -------- device scratch (no allocations allowed) --------
__device__ float d_g[(size_t)MROWS*GG];
__device__ float d_PQ[2*NA*NB*HH];
__device__ float d_Wg[GG*HH];
__device__ float d_b0[HH];
__device__ float d_eP[NA*NB];
__device__ float d_part[(size_t)MROWS*16];     // per-(row, n-tile, col-half) partial dots
__device__ unsigned d_fHiA[AW];
__device__ unsigned d_fLoA[AW];
__device__ unsigned d_fHiB[AW];
__device__ unsigned d_fLoB[AW];
__device__ unsigned d_Wt[6*WW];

__device__ __forceinline__ float gelu_exact(float x) { return x * normcdff(x); }

__device__ __forceinline__ unsigned smem_u32(const void* p) {
    unsigned a;
    asm("{ .reg .u64 t; cvta.to.shared.u64 t, %1; cvt.u32.u64 %0, t; }" : "=r"(a) : "l"(p));
    return a;
}
__device__ __forceinline__ void cp16(unsigned saddr, const void* g) {
    asm volatile("cp.async.cg.shared.global [%0], [%1], 16;" :: "r"(saddr), "l"(g));
}
__device__ __forceinline__ void ldsm4(unsigned addr, unsigned* r) {
    asm volatile("ldmatrix.sync.aligned.m8n8.x4.shared.b16 {%0,%1,%2,%3}, [%4];"
                 : "=r"(r[0]), "=r"(r[1]), "=r"(r[2]), "=r"(r[3]) : "r"(addr));
}
__device__ __forceinline__ void mma16816(float* c, const unsigned* a, unsigned b0, unsigned b1) {
    asm volatile("mma.sync.aligned.m16n8k16.row.col.f32.f16.f16.f32 "
                 "{%0,%1,%2,%3}, {%4,%5,%6,%7}, {%8,%9}, {%0,%1,%2,%3};"
                 : "+f"(c[0]), "+f"(c[1]), "+f"(c[2]), "+f"(c[3])
                 : "r"(a[0]), "r"(a[1]), "r"(a[2]), "r"(a[3]), "r"(b0), "r"(b1));
}
__device__ __forceinline__ unsigned pack_hi(float v0, float v1, float& l0, float& l1) {
    __half a = __float2half_rn(v0), b = __float2half_rn(v1);
    l0 = v0 - __half2float(a);
    l1 = v1 - __half2float(b);
    return ((unsigned)__half_as_ushort(b) << 16) | __half_as_ushort(a);
}
__device__ __forceinline__ unsigned pack_lo(float l0, float l1) {
    return ((unsigned)__half_as_ushort(__float2half_rn(l1)) << 16)
         | __half_as_ushort(__float2half_rn(l0));
}
__device__ __forceinline__ unsigned pack_h(float v0, float v1) {
    return ((unsigned)__half_as_ushort(__float2half_rn(v1)) << 16)
         | __half_as_ushort(__float2half_rn(v0));
}
__device__ __forceinline__ float hf_lo(unsigned w) {
    return __half2float(__ushort_as_half((unsigned short)(w & 0xffffu)));
}
__device__ __forceinline__ float hf_hi(unsigned w) {
    return __half2float(__ushort_as_half((unsigned short)(w >> 16)));
}

// ================= prologue kernels =================
__global__ void rbf_kernel(const float* __restrict__ dist) {
    int idx = blockIdx.x * blockDim.x + threadIdx.x;
    if (idx >= MROWS * GG) return;
    int m = idx / GG, k = idx - m * GG;
    const float delta = 12.0f / 49.0f;
    const float coeff = -0.5f / (delta * delta);
    float t = dist[m] - delta * (float)k;
    d_g[idx] = expf(coeff * t * t);
}

__global__ void bias0_kernel(const float* __restrict__ Win3,
                             const float* __restrict__ bin,
                             const float* __restrict__ rbf_b) {
    int h = blockIdx.x * blockDim.x + threadIdx.x;
    if (h >= HH) return;
    float s = bin[h];
    for (int e = 0; e < EE; e++) s += rbf_b[e] * Win3[(size_t)e * HH + h];
    d_b0[h] = s;
}

#define SBM 64
#define SBN 64
#define SBK 16
__global__ __launch_bounds__(256)
void sgemm64(const float* __restrict__ A, const float* __restrict__ W,
             float* __restrict__ out, int M, int N, int K,
             size_t wstride, size_t ostride)
{
    W += blockIdx.z * wstride;
    out += blockIdx.z * ostride;
    __shared__ float As[SBK][SBM];
    __shared__ float Bs[SBK][SBN];
    int tid = threadIdx.x;
    int tx = tid & 15, ty = tid >> 4;
    int bm = blockIdx.x * SBM, bn = blockIdx.y * SBN;
    float acc[4][4] = {};
    int arow = tid >> 2, acol = (tid & 3) * 4;
    int brow = tid >> 4, bcol = (tid & 15) * 4;
    for (int k0 = 0; k0 < K; k0 += SBK) {
        float4 va = make_float4(0.f, 0.f, 0.f, 0.f);
        if (bm + arow < M) va = *(const float4*)(A + (size_t)(bm + arow) * K + k0 + acol);
        As[acol + 0][arow] = va.x; As[acol + 1][arow] = va.y;
        As[acol + 2][arow] = va.z; As[acol + 3][arow] = va.w;
        *(float4*)&Bs[brow][bcol] = *(const float4*)(W + (size_t)(k0 + brow) * N + bn + bcol);
        __syncthreads();
        #pragma unroll
        for (int kk = 0; kk < SBK; kk++) {
            float a[4], b[4];
            #pragma unroll
            for (int i = 0; i < 4; i++) a[i] = As[kk][ty * 4 + i];
            #pragma unroll
            for (int j = 0; j < 4; j++) b[j] = Bs[kk][tx * 4 + j];
            #pragma unroll
            for (int i = 0; i < 4; i++)
                #pragma unroll
                for (int j = 0; j < 4; j++)
                    acc[i][j] = fmaf(a[i], b[j], acc[i][j]);
        }
        __syncthreads();
    }
    #pragma unroll
    for (int i = 0; i < 4; i++) {
        int row = bm + ty * 4 + i;
        if (row < M)
            #pragma unroll
            for (int j = 0; j < 4; j++)
                out[(size_t)row * N + bn + tx * 4 + j] = acc[i][j];
    }
}

// h0: write gelu(g@Wg + P + Q + b0) directly as fp16 hi/lo split
__global__ __launch_bounds__(256)
void h0_kernel(unsigned* __restrict__ oHi, unsigned* __restrict__ oLo)
{
    __shared__ float Gs[64][52];
    __shared__ float Ws[52][64];
    int tid = threadIdx.x;
    int bm = blockIdx.x * 64, bn = blockIdx.y * 64;
    for (int idx = tid; idx < 64 * GG; idx += 256) {
        int r = idx / GG, k = idx - r * GG;
        Gs[r][k] = d_g[(size_t)(bm + r) * GG + k];
    }
    for (int idx = tid; idx < GG * 64; idx += 256) {
        int k = idx >> 6, n = idx & 63;
        Ws[k][n] = d_Wg[k * HH + bn + n];
    }
    __syncthreads();
    int tx = tid & 15, ty = tid >> 4;
    float acc[4][4] = {};
    #pragma unroll 10
    for (int k = 0; k < GG; k++) {
        float a[4], b[4];
        #pragma unroll
        for (int i = 0; i < 4; i++) a[i] = Gs[ty * 4 + i][k];
        #pragma unroll
        for (int j = 0; j < 4; j++) b[j] = Ws[k][tx * 4 + j];
        #pragma unroll
        for (int i = 0; i < 4; i++)
            #pragma unroll
            for (int j = 0; j < 4; j++)
                acc[i][j] = fmaf(a[i], b[j], acc[i][j]);
    }
    const float* P = d_PQ;
    const float* Q = d_PQ + NA * NB * HH;
    #pragma unroll
    for (int i = 0; i < 4; i++) {
        int m = bm + ty * 4 + i;
        int bb = m & (NB - 1);
        int jat = (m / NB) & (NA - 1);
        int iat = m / (NB * NA);
        int col0 = bn + tx * 4;
        float v[4];
        #pragma unroll
        for (int j = 0; j < 4; j++) {
            int col = col0 + j;
            float t = acc[i][j] + P[(iat * NB + bb) * HH + col]
                    + Q[(jat * NB + bb) * HH + col] + d_b0[col];
            v[j] = gelu_exact(t);
        }
        size_t wi = ((size_t)m * HH + col0) >> 1;
        float l0, l1, l2, l3;
        unsigned h0w = pack_hi(v[0], v[1], l0, l1);
        unsigned h1w = pack_hi(v[2], v[3], l2, l3);
        oHi[wi] = h0w; oHi[wi + 1] = h1w;
        oLo[wi] = pack_lo(l0, l1); oLo[wi + 1] = pack_lo(l2, l3);
    }
}

// weight prep: W[K][N] fp32 -> Wt[N][K] single fp16 (u32 k-pairs)
__global__ __launch_bounds__(256)
void prep_w(const float* __restrict__ We, const float* __restrict__ Wf,
            unsigned* __restrict__ wt)
{
    __shared__ float ts[64][33];
    int z = blockIdx.z;
    const float* W = (z < 3) ? We + (size_t)z * HH * HH : Wf + (size_t)(z - 3) * HH * HH;
    int k0 = blockIdx.x * 64, n0 = blockIdx.y * 32;
    int tid = threadIdx.x;
    #pragma unroll
    for (int i = 0; i < 8; i++) {
        int r = (tid >> 5) + i * 8, c = tid & 31;
        ts[r][c] = W[(size_t)(k0 + r) * HH + n0 + c];
    }
    __syncthreads();
    size_t zo = (size_t)z * WW;
    #pragma unroll
    for (int i = 0; i < 4; i++) {
        int on = (tid >> 5) + i * 8;
        int ok = tid & 31;
        float v0 = ts[ok * 2][on], v1 = ts[ok * 2 + 1][on];
        size_t oidx = zo + (size_t)(n0 + on) * (HH / 2) + (k0 >> 1) + ok;
        wt[oidx] = pack_h(v0, v1);
    }
}

// ========= fp16 2-pass mma GEMM layer (R9 shape), 3-stage cp.async =========
// next = res + gelu((Ah+Al)@W^T + bias); res reconstructed from Ah/Al.
// CTA tile 128x128, 256 threads = 8 warps (4m x 2n), warp tile 32x64.
// Last layer: fused partial dot with Wout -> d_part[row*16 + nt_blk*2 + wn].
#define SMSTR 80                   // 64B data + 16B pad (conflict-free ldmatrix)
#define TILEB (128*SMSTR)          // 10240 B
#define NCHUNK 32
#define NSTAGE 3
#define STAGEB (3*TILEB)           // Ah, Al, B per stage
#define DSMEM_BYTES (NSTAGE*STAGEB)  // 92160

__global__ __launch_bounds__(256, 2)
void mma_layer(const uint4* __restrict__ Ah, const uint4* __restrict__ Al,
               const uint4* __restrict__ Bw,
               const float* __restrict__ bias,
               unsigned* __restrict__ oHi, unsigned* __restrict__ oLo,
               const float* __restrict__ wout, float* __restrict__ part,
               int lastLayer)
{
    extern __shared__ char dsm[];
    __shared__ float s_bias[128];
    __shared__ float s_wout[128];
    unsigned base = smem_u32(dsm);

    int tid = threadIdx.x;
    int nt_blk = blockIdx.x, mt_blk = blockIdx.y;
    if (tid < 128) {
        s_bias[tid] = bias[nt_blk * 128 + tid];
        if (lastLayer) s_wout[tid] = wout[nt_blk * 128 + tid];
    }

    int wid = tid >> 5, lane = tid & 31;
    int wm = wid & 3, wn = wid >> 2;

    float acc[2][8][4];
    #pragma unroll
    for (int i = 0; i < 2; i++)
        #pragma unroll
        for (int j = 0; j < 8; j++)
            #pragma unroll
            for (int k = 0; k < 4; k++) acc[i][j][k] = 0.f;

    const uint4* gAh = Ah + (size_t)(mt_blk * 128) * 128;   // 128 uint4 per row
    const uint4* gAl = Al + (size_t)(mt_blk * 128) * 128;
    const uint4* gB  = Bw + (size_t)(nt_blk * 128) * 128;

    int ldrow = tid >> 2, ldseg = tid & 3;
    unsigned ldoff = (unsigned)(ldrow * SMSTR + ldseg * 16);
    unsigned ldoff2 = (unsigned)((ldrow + 64) * SMSTR + ldseg * 16);

    // ldmatrix lane addressing
    int g = lane >> 3, lr = lane & 7;
    unsigned aoff0 = (unsigned)((wm * 32 + (g & 1) * 8 + lr) * SMSTR + (g >> 1) * 16);
    unsigned boff0 = (unsigned)((wn * 64 + (g >> 1) * 8 + lr) * SMSTR + (g & 1) * 16);

    // issue chunks 0 and 1
    #pragma unroll
    for (int pc = 0; pc < 2; pc++) {
        unsigned sb = base + pc * STAGEB;
        size_t s1 = (size_t)ldrow * 128 + pc * 4 + ldseg;
        size_t s2 = (size_t)(ldrow + 64) * 128 + pc * 4 + ldseg;
        cp16(sb + ldoff, gAh + s1);             cp16(sb + ldoff2, gAh + s2);
        cp16(sb + TILEB + ldoff, gAl + s1);     cp16(sb + TILEB + ldoff2, gAl + s2);
        cp16(sb + 2*TILEB + ldoff, gB + s1);    cp16(sb + 2*TILEB + ldoff2, gB + s2);
        asm volatile("cp.async.commit_group;");
    }

    int stage = 0;
    for (int kc = 0; kc < NCHUNK; kc++) {
        if (kc + 2 < NCHUNK) {
            int ps = (stage + 2) % NSTAGE;
            unsigned sb = base + ps * STAGEB;
            size_t s1 = (size_t)ldrow * 128 + (kc + 2) * 4 + ldseg;
            size_t s2 = (size_t)(ldrow + 64) * 128 + (kc + 2) * 4 + ldseg;
            cp16(sb + ldoff, gAh + s1);             cp16(sb + ldoff2, gAh + s2);
            cp16(sb + TILEB + ldoff, gAl + s1);     cp16(sb + TILEB + ldoff2, gAl + s2);
            cp16(sb + 2*TILEB + ldoff, gB + s1);    cp16(sb + 2*TILEB + ldoff2, gB + s2);
            asm volatile("cp.async.commit_group;");
            asm volatile("cp.async.wait_group 2;");
        } else if (kc + 1 < NCHUNK) {
            asm volatile("cp.async.wait_group 1;");
        } else {
            asm volatile("cp.async.wait_group 0;");
        }
        __syncthreads();

        unsigned bb = base + stage * STAGEB;
        #pragma unroll
        for (int ks = 0; ks < 2; ks++) {
            unsigned kkb = ks * 32;   // 16 fp16 = 32 bytes
            unsigned ah[2][4], al[2][4], b[4][4];
            #pragma unroll
            for (int mt = 0; mt < 2; mt++) {
                unsigned ao = aoff0 + kkb + mt * (16 * SMSTR);
                ldsm4(bb + ao, ah[mt]);
                ldsm4(bb + TILEB + ao, al[mt]);
            }
            #pragma unroll
            for (int p = 0; p < 4; p++)
                ldsm4(bb + 2 * TILEB + boff0 + kkb + p * (16 * SMSTR), b[p]);
            #pragma unroll
            for (int mt = 0; mt < 2; mt++)
                #pragma unroll
                for (int nt = 0; nt < 8; nt++)
                    mma16816(acc[mt][nt], ah[mt], b[nt >> 1][(nt & 1) * 2], b[nt >> 1][(nt & 1) * 2 + 1]);
            #pragma unroll
            for (int mt = 0; mt < 2; mt++)
                #pragma unroll
                for (int nt = 0; nt < 8; nt++)
                    mma16816(acc[mt][nt], al[mt], b[nt >> 1][(nt & 1) * 2], b[nt >> 1][(nt & 1) * 2 + 1]);
        }
        __syncthreads();
        stage = (stage + 1) % NSTAGE;
    }

    // epilogue: residual reconstructed from A hi/lo at the output columns
    const unsigned* rAh = (const unsigned*)Ah;
    const unsigned* rAl = (const unsigned*)Al;
    #pragma unroll
    for (int mt = 0; mt < 2; mt++) {
        #pragma unroll
        for (int half = 0; half < 2; half++) {
            int row = mt_blk * 128 + wm * 32 + mt * 16 + half * 8 + (lane >> 2);
            float pdot = 0.f;
            #pragma unroll
            for (int nt = 0; nt < 8; nt++) {
                int cl = wn * 64 + nt * 8 + (lane & 3) * 2;
                size_t gi = (size_t)row * HH + nt_blk * 128 + cl;
                size_t wi = gi >> 1;
                unsigned hw = rAh[wi], lw = rAl[wi];
                float r0 = hf_lo(hw) + hf_lo(lw);
                float r1 = hf_hi(hw) + hf_hi(lw);
                float v0 = r0 + gelu_exact(acc[mt][nt][half * 2 + 0] + s_bias[cl]);
                float v1 = r1 + gelu_exact(acc[mt][nt][half * 2 + 1] + s_bias[cl + 1]);
                if (lastLayer) {
                    pdot += v0 * s_wout[cl] + v1 * s_wout[cl + 1];
                } else {
                    float l0, l1;
                    unsigned ohw = pack_hi(v0, v1, l0, l1);
                    oHi[wi] = ohw;
                    oLo[wi] = pack_lo(l0, l1);
                }
            }
            if (lastLayer) {
                pdot += __shfl_xor_sync(0xffffffffu, pdot, 1);
                pdot += __shfl_xor_sync(0xffffffffu, pdot, 2);
                if ((lane & 3) == 0)
                    part[(size_t)row * 16 + nt_blk * 2 + wn] = pdot;
            }
        }
    }
}

// ========= final reduction over partial dots (2MB input, deterministic) =========
__global__ __launch_bounds__(128)
void reduce2(const float* __restrict__ part, const float* __restrict__ bout,
             const int* __restrict__ mask, const float* __restrict__ vec_hat,
             float* __restrict__ out, int mode)
{
    __shared__ float sred[4][4];
    int tid = threadIdx.x;
    int jb = blockIdx.x;
    int j = jb / NB, b = jb % NB;
    int warp = tid >> 5, lane = tid & 31;
    float bo = bout[0];
    bool mj = mask[b * NA + j] != 0;

    int i = tid;   // 0..127 = one atom index each
    size_t m = ((size_t)(i * NA + j)) * NB + b;
    float dot = 0.f;
    #pragma unroll
    for (int t = 0; t < 16; t++) dot += part[m * 16 + t];
    float entry = (mj && mask[b * NA + i] != 0) ? 1.0f : 0.0f;
    float val = (dot + bo) * entry;

    float e = val, fx = 0.f, fy = 0.f, fz = 0.f;
    if (mode == 1) {
        const float* v = vec_hat + m * 3;
        fx = val * v[0]; fy = val * v[1]; fz = val * v[2];
    }
    #pragma unroll
    for (int o = 16; o > 0; o >>= 1) {
        e  += __shfl_xor_sync(0xffffffffu, e,  o);
        fx += __shfl_xor_sync(0xffffffffu, fx, o);
        fy += __shfl_xor_sync(0xffffffffu, fy, o);
        fz += __shfl_xor_sync(0xffffffffu, fz, o);
    }
    if (lane == 0) { sred[warp][0] = e; sred[warp][1] = fx; sred[warp][2] = fy; sred[warp][3] = fz; }
    __syncthreads();
    if (tid == 0) {
        float a0 = 0, a1 = 0, a2 = 0, a3 = 0;
        for (int w = 0; w < 4; w++) { a0 += sred[w][0]; a1 += sred[w][1]; a2 += sred[w][2]; a3 += sred[w][3]; }
        if (mode == 0) d_eP[jb] = a0;
        else {
            int o = 2 + (b * NA + j) * 3;
            out[o + 0] = a1 / 60.0f; out[o + 1] = a2 / 60.0f; out[o + 2] = a3 / 60.0f;
        }
    }
}

__global__ void energy_kernel(float* __restrict__ out) {
    int tid = threadIdx.x;
    int b = tid >> 5, lane = tid & 31;
    if (b >= NB) return;
    float s = 0.f;
    for (int j = lane; j < NA; j += 32) s += d_eP[j * NB + b];
    #pragma unroll
    for (int o = 16; o > 0; o >>= 1) s += __shfl_xor_sync(0xffffffffu, s, o);
    if (lane == 0) out[b] = s / 3600.0f;
}

// ========= launch =========
extern "C" void kernel_launch(void* const* d_in, const int* in_sizes, int n_in,
                              void* d_out, int out_size)
{
    const float* x       = (const float*)d_in[0];
    const float* dist    = (const float*)d_in[1];
    const float* vec_hat = (const float*)d_in[2];
    const int*   mask    = (const int*)d_in[3];   // bool promoted to int32
    const float* rbf_W   = (const float*)d_in[4];
    const float* rbf_b   = (const float*)d_in[5];
    const float* Win[2]  = {(const float*)d_in[6],  (const float*)d_in[12]};
    const float* bin[2]  = {(const float*)d_in[7],  (const float*)d_in[13]};
    const float* Wh[2]   = {(const float*)d_in[8],  (const float*)d_in[14]};
    const float* bh[2]   = {(const float*)d_in[9],  (const float*)d_in[15]};
    const float* Wout[2] = {(const float*)d_in[10], (const float*)d_in[16]};
    const float* bout[2] = {(const float*)d_in[11], (const float*)d_in[17]};
    int L = in_sizes[8] / (HH * HH);
    float* out = (float*)d_out;

    static int attr_set = 0;
    if (!attr_set) {
        cudaFuncSetAttribute(mma_layer, cudaFuncAttributeMaxDynamicSharedMemorySize, DSMEM_BYTES);
        attr_set = 1;
    }

    float *PQ, *Wg, *partp;
    unsigned *fHiA, *fLoA, *fHiB, *fLoB, *Wt;
    cudaGetSymbolAddress((void**)&PQ, d_PQ);
    cudaGetSymbolAddress((void**)&Wg, d_Wg);
    cudaGetSymbolAddress((void**)&partp, d_part);
    cudaGetSymbolAddress((void**)&fHiA, d_fHiA);
    cudaGetSymbolAddress((void**)&fLoA, d_fLoA);
    cudaGetSymbolAddress((void**)&fHiB, d_fHiB);
    cudaGetSymbolAddress((void**)&fLoB, d_fLoB);
    cudaGetSymbolAddress((void**)&Wt, d_Wt);

    rbf_kernel<<<(MROWS * GG + 255) / 256, 256>>>(dist);
    prep_w<<<dim3(16, 32, 6), 256>>>(Wh[0], Wh[1], Wt);

    for (int mlp = 0; mlp < 2; mlp++) {
        const float* W1 = Win[mlp];
        const float* W3 = Win[mlp] + (size_t)2 * EE * HH;

        // P and Q in one launch (z selects Win row-slice + output half)
        sgemm64<<<dim3(4, 16, 2), 256>>>(x, W1, PQ, NA * NB, HH, EE,
                                         (size_t)EE * HH, (size_t)NA * NB * HH);
        sgemm64<<<dim3(1, 16, 1), 256>>>(rbf_W, W3, Wg, GG, HH, EE, 0, 0);
        bias0_kernel<<<4, 256>>>(W3, bin[mlp], rbf_b);

        h0_kernel<<<dim3(MROWS / 64, HH / 64), 256>>>(fHiA, fLoA);

        unsigned* curHi = fHiA; unsigned* curLo = fLoA;
        unsigned* nxtHi = fHiB; unsigned* nxtLo = fLoB;
        for (int l = 0; l < L; l++) {
            size_t zo = (size_t)(mlp * 3 + l) * WW;
            int last = (l == L - 1) ? 1 : 0;
            mma_layer<<<dim3(HH / 128, MROWS / 128), 256, DSMEM_BYTES>>>(
                (const uint4*)curHi, (const uint4*)curLo,
                (const uint4*)(Wt + zo),
                bh[mlp] + (size_t)l * HH, nxtHi, nxtLo,
                Wout[mlp], partp, last);
            unsigned* t1 = curHi; curHi = nxtHi; nxtHi = t1;
            unsigned* t2 = curLo; curLo = nxtLo; nxtLo = t2;
        }

        reduce2<<<NA * NB, 128>>>(partp, bout[mlp], mask, vec_hat, out, mlp);
    }

    energy_kernel<<<1, 64>>>(out);
}